// round 3
// baseline (speedup 1.0000x reference)
#include <cuda_runtime.h>

// Problem constants
#define BB 4096   // batch
#define NN 2048   // features
#define FF 64     // fields
#define KK 64     // latent dim

// GEMM tiling
#define MTILE    128
#define KC       32
#define SPLITS   8
#define KRANGE   (NN / SPLITS)    // 256 features per split
#define NCHUNK   (KRANGE / KC)    // 8 chunks per CTA
#define NTHREADS 128

// Static device scratch (no runtime allocation allowed)
__device__ float  g_V[NN * KK];                 // gathered V[i, f2f[i]]  [N, K]
__device__ float  g_vnorm[NN];                  // ||V_i||^2
__device__ float  g_Zpart[SPLITS * BB * KK];    // split-K partials, layout [sp][n][m]
__device__ float  g_lin[BB];                    // linear partials
__device__ double g_sumZ2;
__device__ double g_diag;

// ---------- packed f32x2 helpers ----------
__device__ __forceinline__ unsigned long long pack_dup(float v) {
    unsigned long long r;
    asm("mov.b64 %0, {%1, %1};" : "=l"(r) : "f"(v));
    return r;
}
__device__ __forceinline__ void fma2(unsigned long long& acc,
                                     unsigned long long a,
                                     unsigned long long b) {
    asm("fma.rn.f32x2 %0, %1, %2, %0;" : "+l"(acc) : "l"(a), "l"(b));
}
__device__ __forceinline__ float2 unpack2(unsigned long long v) {
    float2 f;
    asm("mov.b64 {%0, %1}, %2;" : "=f"(f.x), "=f"(f.y) : "l"(v));
    return f;
}

// ---------- Kernel 0: zero accumulators ----------
__global__ void ffm_zero() {
    int idx = blockIdx.x * blockDim.x + threadIdx.x;
    if (idx < BB) g_lin[idx] = 0.0f;
    if (idx == 0) { g_sumZ2 = 0.0; g_diag = 0.0; }
}

// ---------- Kernel 1: gather V and compute ||V_i||^2 ----------
__global__ void ffm_gather(const float* __restrict__ vec,
                           const int* __restrict__ f2f) {
    __shared__ float sred[64];
    int i = blockIdx.x;       // feature
    int n = threadIdx.x;      // latent index 0..63
    int f = f2f[i];
    float v = vec[((size_t)i * FF + f) * KK + n];
    g_V[i * KK + n] = v;
    sred[n] = v * v;
    __syncthreads();
    #pragma unroll
    for (int s = 32; s > 0; s >>= 1) {
        if (n < s) sred[n] += sred[n + s];
        __syncthreads();
    }
    if (n == 0) g_vnorm[i] = sred[0];
}

// ---------- Kernel 2: fused GEMM + linear + diag ----------
// 256 CTAs = 32 m-tiles x 8 k-splits, 128 threads.
// Per-thread microtile: 8 m (4 f32x2 pairs) x 8 n.
__global__ void __launch_bounds__(NTHREADS, 2)
ffm_main(const float* __restrict__ X, const float* __restrict__ W) {
    __shared__ __align__(16) float Xs[KC][MTILE + 4];              // ld 132 (528 B)
    __shared__ __align__(16) unsigned long long Vsd[KC][KK + 2];   // dup'd pairs, ld 66 (528 B)
    __shared__ __align__(16) float Ws[KRANGE];
    __shared__ __align__(16) float vns[KRANGE];
    __shared__ double red[NTHREADS];

    const int tid   = threadIdx.x;
    const int mt    = blockIdx.x & (BB / MTILE - 1);   // 0..31
    const int sp    = blockIdx.x / (BB / MTILE);       // 0..7
    const int mbase = mt * MTILE;
    const int ibase = sp * KRANGE;

    for (int t = tid; t < KRANGE; t += NTHREADS) {
        Ws[t]  = W[ibase + t];
        vns[t] = g_vnorm[ibase + t];
    }
    __syncthreads();

    unsigned long long acc[4][8];
    #pragma unroll
    for (int a = 0; a < 4; a++)
        #pragma unroll
        for (int n = 0; n < 8; n++) acc[a][n] = 0ull;

    float lin[8];
    #pragma unroll
    for (int j = 0; j < 8; j++) lin[j] = 0.0f;
    double diagd = 0.0;

    const int tx = tid & 7;     // n group
    const int ty = tid >> 3;    // m group
    const int m0 = ty * 8;
    const int na = tx * 4;          // first 4 n
    const int nb = 32 + tx * 4;     // second 4 n

    for (int cc = 0; cc < NCHUNK; cc++) {
        const int i0 = ibase + cc * KC;
        const int ic = cc * KC;

        // V tile [KC x 64] -> duplicated-pair form
        #pragma unroll
        for (int j = 0; j < 4; j++) {
            int idx = tid + j * NTHREADS;        // 0..511
            int vk  = idx >> 4;                  // 0..31
            int vc  = (idx & 15) << 2;           // 0..60
            float4 v4 = *(const float4*)&g_V[(size_t)(i0 + vk) * KK + vc];
            ulonglong2 d0; d0.x = pack_dup(v4.x); d0.y = pack_dup(v4.y);
            ulonglong2 d1; d1.x = pack_dup(v4.z); d1.y = pack_dup(v4.w);
            *(ulonglong2*)&Vsd[vk][vc]     = d0;
            *(ulonglong2*)&Vsd[vk][vc + 2] = d1;
        }

        // X tile [128 x KC] transposed, fused linear + diag terms
        #pragma unroll
        for (int j = 0; j < 8; j++) {
            int idx = tid + j * NTHREADS;
            int r   = idx >> 3;                  // 0..127
            int c   = (idx & 7) << 2;            // 0..28
            const float4 x4 = *(const float4*)&X[(size_t)(mbase + r) * NN + (i0 + c)];
            const float4 w4 = *(const float4*)&Ws[ic + c];
            const float4 n4 = *(const float4*)&vns[ic + c];
            lin[j] += x4.x * w4.x + x4.y * w4.y + x4.z * w4.z + x4.w * w4.w;
            diagd += (double)(x4.x * x4.x * n4.x + x4.y * x4.y * n4.y +
                              x4.z * x4.z * n4.z + x4.w * x4.w * n4.w);
            Xs[c + 0][r] = x4.x;
            Xs[c + 1][r] = x4.y;
            Xs[c + 2][r] = x4.z;
            Xs[c + 3][r] = x4.w;
        }
        __syncthreads();

        #pragma unroll 4
        for (int k = 0; k < KC; k++) {
            const ulonglong2 a01 = *(const ulonglong2*)&Xs[k][m0];       // pairs (m0..m0+3)
            const ulonglong2 a23 = *(const ulonglong2*)&Xs[k][m0 + 4];   // pairs (m0+4..m0+7)
            const ulonglong2 b01 = *(const ulonglong2*)&Vsd[k][na];
            const ulonglong2 b23 = *(const ulonglong2*)&Vsd[k][na + 2];
            const ulonglong2 b45 = *(const ulonglong2*)&Vsd[k][nb];
            const ulonglong2 b67 = *(const ulonglong2*)&Vsd[k][nb + 2];
            unsigned long long bd[8] = { b01.x, b01.y, b23.x, b23.y,
                                         b45.x, b45.y, b67.x, b67.y };
            #pragma unroll
            for (int n = 0; n < 8; n++) {
                fma2(acc[0][n], a01.x, bd[n]);
                fma2(acc[1][n], a01.y, bd[n]);
                fma2(acc[2][n], a23.x, bd[n]);
                fma2(acc[3][n], a23.y, bd[n]);
            }
        }
        __syncthreads();
    }

    // Emit split-K partial Z, layout [sp][n][m] -> coalesced float2 stores
    float* zp = &g_Zpart[(size_t)sp * BB * KK];
    #pragma unroll
    for (int n = 0; n < 8; n++) {
        int gn = (n < 4) ? (na + n) : (nb + (n - 4));
        #pragma unroll
        for (int mp = 0; mp < 4; mp++) {
            float2 z = unpack2(acc[mp][n]);
            *(float2*)&zp[(size_t)gn * BB + (mbase + m0 + mp * 2)] = z;
        }
    }

    // Linear partials
    #pragma unroll
    for (int j = 0; j < 8; j++) {
        int r = (tid + j * NTHREADS) >> 3;
        atomicAdd(&g_lin[mbase + r], lin[j]);
    }

    // Diag partial: fp64 block reduce, one atomic per CTA
    red[tid] = diagd;
    __syncthreads();
    for (int s = NTHREADS / 2; s > 0; s >>= 1) {
        if (tid < s) red[tid] += red[tid + s];
        __syncthreads();
    }
    if (tid == 0) atomicAdd(&g_diag, red[0]);
}

// ---------- Kernel 3: combine split-K partials, reduce sum(Z^2) in fp64 ----------
__global__ void ffm_reduce() {
    __shared__ double red[256];
    double local = 0.0;
    const int stride = gridDim.x * blockDim.x;
    for (int e = blockIdx.x * blockDim.x + threadIdx.x; e < BB * KK; e += stride) {
        float z = 0.0f;
        #pragma unroll
        for (int s = 0; s < SPLITS; s++) z += g_Zpart[(size_t)s * BB * KK + e];
        local += (double)z * (double)z;
    }
    red[threadIdx.x] = local;
    __syncthreads();
    for (int s = 128; s > 0; s >>= 1) {
        if (threadIdx.x < s) red[threadIdx.x] += red[threadIdx.x + s];
        __syncthreads();
    }
    if (threadIdx.x == 0) atomicAdd(&g_sumZ2, red[0]);
}

// ---------- Kernel 4: write output ----------
__global__ void ffm_out(const float* __restrict__ bias, float* __restrict__ out) {
    int i = blockIdx.x * blockDim.x + threadIdx.x;
    if (i < BB) {
        double inter = 0.5 * (g_sumZ2 - g_diag);
        out[i] = (float)((double)g_lin[i] + (double)bias[0] + inter);
    }
}

extern "C" void kernel_launch(void* const* d_in, const int* in_sizes, int n_in,
                              void* d_out, int out_size) {
    const float* X    = (const float*)d_in[0];   // [B, N]
    const float* W    = (const float*)d_in[1];   // [1, N]
    const float* b    = (const float*)d_in[2];   // [1]
    const float* vec  = (const float*)d_in[3];   // [N, F, K]
    const int*   f2f  = (const int*)d_in[4];     // [N]
    float* out = (float*)d_out;                  // [B, 1]
    (void)in_sizes; (void)n_in; (void)out_size;

    ffm_zero<<<(BB + 255) / 256, 256>>>();
    ffm_gather<<<NN, 64>>>(vec, f2f);
    ffm_main<<<(BB / MTILE) * SPLITS, NTHREADS>>>(X, W);
    ffm_reduce<<<256, 256>>>();
    ffm_out<<<(BB + 255) / 256, 256>>>(b, out);
}

// round 5
// speedup vs baseline: 1.4224x; 1.4224x over previous
#include <cuda_runtime.h>

// Problem constants
#define BB 4096   // batch
#define NN 2048   // features
#define FF 64     // fields
#define KK 64     // latent dim

// GEMM tiling
#define MTILE    64
#define KC       32
#define SPLITS   4
#define KRANGE   (NN / SPLITS)    // 512 features per split
#define NCHUNK   (KRANGE / KC)    // 16 chunks per CTA
#define NTHREADS 128

// Static device scratch (16B-aligned: accessed via float4)
__device__ __align__(16) float  g_Vt[KK * NN];                // V transposed: [n][i]
__device__ __align__(16) float  g_vnorm[NN];                  // ||V_i||^2
__device__ __align__(16) float  g_Zpart[SPLITS * BB * KK];    // split-K partials
__device__ __align__(16) float  g_lin[BB];                    // linear partials
__device__ double g_sumZ2;
__device__ double g_diag;

// ---------- packed f32x2 helpers ----------
__device__ __forceinline__ void fma2(unsigned long long& acc,
                                     unsigned long long a,
                                     unsigned long long b) {
    asm("fma.rn.f32x2 %0, %1, %2, %0;" : "+l"(acc) : "l"(a), "l"(b));
}
__device__ __forceinline__ float hsum2(unsigned long long v) {
    float lo, hi;
    asm("mov.b64 {%0, %1}, %2;" : "=f"(lo), "=f"(hi) : "l"(v));
    return lo + hi;
}

// ---------- Kernel 1: gather V (transposed) + vnorm + zero accumulators ----------
// 32 blocks x 256 threads; block handles 64 features x 64 latents.
__global__ void ffm_gather(const float* __restrict__ vec,
                           const int* __restrict__ f2f) {
    __shared__ float T[64][65];
    __shared__ float pr[64][4];
    const int t  = threadIdx.x;
    const int i0 = blockIdx.x * 64;

    // load phase: thread covers feature il, latent segment ns..ns+15
    {
        const int il = t >> 2;
        const int ns = (t & 3) * 16;
        const int i  = i0 + il;
        const int f  = f2f[i];
        const float* src = vec + ((size_t)i * FF + f) * KK + ns;
        float p = 0.0f;
        #pragma unroll
        for (int q = 0; q < 16; q += 4) {
            float4 v = *(const float4*)(src + q);
            T[il][ns + q + 0] = v.x;
            T[il][ns + q + 1] = v.y;
            T[il][ns + q + 2] = v.z;
            T[il][ns + q + 3] = v.w;
            p += v.x * v.x + v.y * v.y + v.z * v.z + v.w * v.w;
        }
        pr[il][t & 3] = p;
    }
    __syncthreads();

    if (t < 64)
        g_vnorm[i0 + t] = pr[t][0] + pr[t][1] + pr[t][2] + pr[t][3];

    // write phase: thread covers latent n, feature segment is..is+15 (coalesced)
    {
        const int n  = t >> 2;
        const int is = (t & 3) * 16;
        float* dst = g_Vt + (size_t)n * NN + i0 + is;
        #pragma unroll
        for (int q = 0; q < 16; q += 4) {
            float4 w;
            w.x = T[is + q + 0][n];
            w.y = T[is + q + 1][n];
            w.z = T[is + q + 2][n];
            w.w = T[is + q + 3][n];
            *(float4*)(dst + q) = w;
        }
    }

    // zero accumulators (32 blocks x 128 covers g_lin[4096])
    if (t < 128) g_lin[blockIdx.x * 128 + t] = 0.0f;
    if (blockIdx.x == 0 && t == 0) { g_sumZ2 = 0.0; g_diag = 0.0; }
}

// ---------- Kernel 2: fused GEMM (split-K) + linear + diag ----------
// grid = 64 m-tiles x 4 splits = 256 CTAs, 128 threads.
// Per-thread microtile: 4m x 8n, k accumulated in f32x2 pairs.
__global__ void __launch_bounds__(NTHREADS, 2)
ffm_main(const float* __restrict__ X, const float* __restrict__ W) {
    __shared__ __align__(16) float Xs[MTILE][KC + 2];   // row stride 34 words (136 B)
    __shared__ __align__(16) float Vs[KK][KC + 2];
    __shared__ __align__(16) float Ws[KRANGE];
    __shared__ __align__(16) float vns[KRANGE];
    __shared__ double red[NTHREADS];

    const int tid   = threadIdx.x;
    const int mt    = blockIdx.x & 63;      // 0..63
    const int sp    = blockIdx.x >> 6;      // 0..3
    const int mbase = mt * MTILE;
    const int ibase = sp * KRANGE;

    for (int t = tid; t < KRANGE; t += NTHREADS) {
        Ws[t]  = W[ibase + t];
        vns[t] = g_vnorm[ibase + t];
    }

    const int tx = tid & 7;     // n group
    const int ty = tid >> 3;    // 0..15
    const int m0 = ty * 4;

    unsigned long long acc[4][8];
    #pragma unroll
    for (int i = 0; i < 4; i++)
        #pragma unroll
        for (int j = 0; j < 8; j++) acc[i][j] = 0ull;

    float lin[4] = {0.f, 0.f, 0.f, 0.f};
    double diagd = 0.0;

    float4 xr[4], vr[4];
    const int c4 = tx * 4;

    auto LOADX = [&](int cc) {
        const int icol = ibase + cc * KC + c4;
        #pragma unroll
        for (int it = 0; it < 4; it++) {
            const int r = ty + it * 16;
            xr[it] = *(const float4*)&X[(size_t)(mbase + r) * NN + icol];
            vr[it] = *(const float4*)&g_Vt[(size_t)r * NN + icol];
        }
    };
    // NOTE: smem row stride is 34 words -> odd rows are 8-mod-16 aligned.
    // Use 8-byte (float2) stores, which are always legal here.
    auto STORE = [&](int cc) {
        const int ic = cc * KC;
        const float4 w4 = *(const float4*)&Ws[ic + c4];
        const float4 n4 = *(const float4*)&vns[ic + c4];
        #pragma unroll
        for (int it = 0; it < 4; it++) {
            const int r = ty + it * 16;
            const float4 x4 = xr[it];
            const float4 v4 = vr[it];
            lin[it] += x4.x * w4.x + x4.y * w4.y + x4.z * w4.z + x4.w * w4.w;
            diagd += (double)(x4.x * x4.x * n4.x + x4.y * x4.y * n4.y +
                              x4.z * x4.z * n4.z + x4.w * x4.w * n4.w);
            float2* px = (float2*)&Xs[r][c4];
            px[0] = make_float2(x4.x, x4.y);
            px[1] = make_float2(x4.z, x4.w);
            float2* pv = (float2*)&Vs[r][c4];
            pv[0] = make_float2(v4.x, v4.y);
            pv[1] = make_float2(v4.z, v4.w);
        }
    };

    LOADX(0);
    __syncthreads();   // Ws/vns visible
    STORE(0);
    __syncthreads();

    for (int cc = 0; cc < NCHUNK; cc++) {
        if (cc + 1 < NCHUNK) LOADX(cc + 1);

        #pragma unroll 4
        for (int kp = 0; kp < KC / 2; kp++) {
            const int k = kp * 2;
            unsigned long long a[4], b[8];
            #pragma unroll
            for (int i = 0; i < 4; i++)
                a[i] = *(const unsigned long long*)&Xs[m0 + i][k];
            #pragma unroll
            for (int j = 0; j < 8; j++)
                b[j] = *(const unsigned long long*)&Vs[tx + 8 * j][k];
            #pragma unroll
            for (int j = 0; j < 8; j++)
                #pragma unroll
                for (int i = 0; i < 4; i++)
                    fma2(acc[i][j], a[i], b[j]);
        }
        __syncthreads();
        if (cc + 1 < NCHUNK) {
            STORE(cc + 1);
            __syncthreads();
        }
    }

    // emit split-K partials: per-thread linear block of 32 floats (coalesced STG.128)
    {
        float* zp = g_Zpart + (size_t)sp * (BB * KK) + ((size_t)mt * NTHREADS + tid) * 32;
        #pragma unroll
        for (int i = 0; i < 4; i++) {
            float4 o0, o1;
            o0.x = hsum2(acc[i][0]); o0.y = hsum2(acc[i][1]);
            o0.z = hsum2(acc[i][2]); o0.w = hsum2(acc[i][3]);
            o1.x = hsum2(acc[i][4]); o1.y = hsum2(acc[i][5]);
            o1.z = hsum2(acc[i][6]); o1.w = hsum2(acc[i][7]);
            *(float4*)&zp[i * 8]     = o0;
            *(float4*)&zp[i * 8 + 4] = o1;
        }
    }

    // linear partials
    #pragma unroll
    for (int it = 0; it < 4; it++)
        atomicAdd(&g_lin[mbase + ty + it * 16], lin[it]);

    // diag partial: fp64 block reduce, one atomic per CTA
    red[tid] = diagd;
    __syncthreads();
    for (int s = NTHREADS / 2; s > 0; s >>= 1) {
        if (tid < s) red[tid] += red[tid + s];
        __syncthreads();
    }
    if (tid == 0) atomicAdd(&g_diag, red[0]);
}

// ---------- Kernel 3: combine split-K partials, fp64 reduce sum(Z^2) ----------
// 256 blocks x 256 threads; one float4 per thread, MLP=4 across splits.
__global__ void ffm_reduce() {
    __shared__ double red[256];
    const int gid = blockIdx.x * 256 + threadIdx.x;   // 0..65535
    const float4* p = (const float4*)g_Zpart;
    const int stride4 = (BB * KK) / 4;                // 65536 float4 per split
    float4 z = p[gid];
    #pragma unroll
    for (int s = 1; s < SPLITS; s++) {
        float4 q = p[gid + s * stride4];
        z.x += q.x; z.y += q.y; z.z += q.z; z.w += q.w;
    }
    double local = (double)z.x * z.x + (double)z.y * z.y +
                   (double)z.z * z.z + (double)z.w * z.w;
    red[threadIdx.x] = local;
    __syncthreads();
    for (int s = 128; s > 0; s >>= 1) {
        if (threadIdx.x < s) red[threadIdx.x] += red[threadIdx.x + s];
        __syncthreads();
    }
    if (threadIdx.x == 0) atomicAdd(&g_sumZ2, red[0]);
}

// ---------- Kernel 4: write output ----------
__global__ void ffm_out(const float* __restrict__ bias, float* __restrict__ out) {
    int i = blockIdx.x * blockDim.x + threadIdx.x;
    if (i < BB) {
        double inter = 0.5 * (g_sumZ2 - g_diag);
        out[i] = (float)((double)g_lin[i] + (double)bias[0] + inter);
    }
}

extern "C" void kernel_launch(void* const* d_in, const int* in_sizes, int n_in,
                              void* d_out, int out_size) {
    const float* X   = (const float*)d_in[0];   // [B, N]
    const float* W   = (const float*)d_in[1];   // [1, N]
    const float* b   = (const float*)d_in[2];   // [1]
    const float* vec = (const float*)d_in[3];   // [N, F, K]
    const int*   f2f = (const int*)d_in[4];     // [N]
    float* out = (float*)d_out;                 // [B, 1]
    (void)in_sizes; (void)n_in; (void)out_size;

    ffm_gather<<<NN / 64, 256>>>(vec, f2f);
    ffm_main<<<(BB / MTILE) * SPLITS, NTHREADS>>>(X, W);
    ffm_reduce<<<256, 256>>>();
    ffm_out<<<(BB + 255) / 256, 256>>>(b, out);
}